// round 16
// baseline (speedup 1.0000x reference)
#include <cuda_runtime.h>

#define NT 256
#define NB 3108                    // 7 blocks/SM x 148 SMs x 3 exact waves
#define SPATIAL (256 * 256 * 64)   // 4194304
#define NTOT    (2 * SPATIAL)      // 8388608
#define XS (256 * 64)              // x stride
#define YS 64                      // y stride

__device__ float g_pb[NB];
__device__ float g_pp[NB];
__device__ float g_pd[NB];
__device__ unsigned int g_cnt = 0;

__global__ __launch_bounds__(NT, 7) void loss_kernel(
    const float* __restrict__ outp, const float* __restrict__ tgt,
    float* __restrict__ out)
{
    const float EPS = 1e-10f;
    const float C8  = 0.0125f;        // 0.125 * DX
    const float C6  = 0.1f / 6.0f;    // DX/6
    const float CZ  = 0.0025f;        // 0.25 * DX * DY

    float sb = 0.f, sp = 0.f, sd = 0.f;

    for (int idx = blockIdx.x * NT + threadIdx.x; idx < NTOT; idx += NB * NT) {
        const int b    = idx >> 22;
        const int sidx = idx & (SPATIAL - 1);
        const int z    = sidx & 63;
        const int y    = (sidx >> 6) & 255;
        const int x    = sidx >> 14;

        const float* po = outp + (size_t)b * 3 * SPATIAL + sidx;   // bx_p
        const float* pt = tgt  + (size_t)b * 4 * SPATIAL + sidx;   // bx_t

        // ---- pointwise losses (fast approximate division) ----
        const float bxp = po[0], byp = po[SPATIAL], bzp = po[2 * SPATIAL];
        {
            const float bxt = pt[0], byt = pt[SPATIAL], bzt = pt[2 * SPATIAL];
            const float bxt2 = bxt * bxt, byt2 = byt * byt, bzt2 = bzt * bzt;
            const float t1 = bxp * bxp + byp * byp - bxt2 - byt2;
            sb += __fdividef(t1 * t1, bxt2 + byt2 + EPS);
            const float dv = bzp - bzt;
            const float dv2 = dv * dv;
            sb += __fdividef(dv2 * dv2, bzt2 + EPS);
            const float cr = bxp * byt - byp * bxt;
            sp += __fdividef(cr * cr, bxt2 + byt2 + bzt2 + EPS);
        }

        // ---- divergence flux loss, coefficient-streamed ----
        if (x < 255 && y < 255 && z < 63) {
            // corner c = (i,j,k) -> i*4 + j*2 + k; offset i*XS + j*YS + k
            const float* pz = pt + 3 * SPATIAL;
            const float z0 = pz[0],       z1 = pz[1];
            const float z2 = pz[YS],      z3 = pz[YS + 1];
            const float z4 = pz[XS],      z5 = pz[XS + 1];
            const float z6 = pz[XS + YS], z7 = pz[XS + YS + 1];

            // bx coefficients
            const float q1 =  C8 * (z5 - z4 + z7 - z6);
            const float q2 = -C8 * (z1 - z0 + z3 - z2);
            const float r1 =  C6 * (z1 - z5);
            const float r2 =  C6 * (z3 - z7);
            const float r3 =  C6 * (z4 - z0);
            const float r4 =  C6 * (z6 - z2);
            // by coefficients
            const float s1 =  C8 * (z3 - z2 + z7 - z6);
            const float s2 = -C8 * (z1 - z0 + z5 - z4);
            const float u1 =  C6 * (z5 - z7);
            const float u2 =  C6 * (z1 - z3);
            const float u3 =  C6 * (z6 - z4);
            const float u4 =  C6 * (z2 - z0);

            float num, bxc, byc, bzc;
            {   // bx batch (c0 reused from pointwise load)
                const float c0 = bxp,         c1 = po[1];
                const float c2 = po[YS],      c3 = po[YS + 1];
                const float c4 = po[XS],      c5 = po[XS + 1];
                const float c6 = po[XS + YS], c7 = po[XS + YS + 1];
                num = c0 * (q2 + r3) + c1 * (q2 + r1)
                    + c2 * (q2 + r4) + c3 * (q2 + r2)
                    + (c4 + c6) * (q1 + (r3 + r4))
                    + (c5 + c7) * (q1 + (r1 + r2));
                bxc = ((c0 + c1) + (c2 + c3)) + ((c4 + c5) + (c6 + c7));
            }
            {   // by batch
                const float* py = po + SPATIAL;
                const float c0 = byp,         c1 = py[1];
                const float c2 = py[YS],      c3 = py[YS + 1];
                const float c4 = py[XS],      c5 = py[XS + 1];
                const float c6 = py[XS + YS], c7 = py[XS + YS + 1];
                num += c0 * (s2 + u4) + c1 * (s2 + u2)
                     + c4 * (s2 + u3) + c5 * (s2 + u1)
                     + (c2 + c6) * (s1 + (u3 + u4))
                     + (c3 + c7) * (s1 + (u1 + u2));
                byc = ((c0 + c1) + (c2 + c3)) + ((c4 + c5) + (c6 + c7));
            }
            {   // bz batch
                const float* pb = po + 2 * SPATIAL;
                const float c0 = bzp,         c1 = pb[1];
                const float c2 = pb[YS],      c3 = pb[YS + 1];
                const float c4 = pb[XS],      c5 = pb[XS + 1];
                const float c6 = pb[XS + YS], c7 = pb[XS + YS + 1];
                num += CZ * (((c1 + c3) + (c5 + c7)) - ((c0 + c2) + (c4 + c6)));
                bzc = ((c0 + c1) + (c2 + c3)) + ((c4 + c5) + (c6 + c7));
            }
            bxc *= 0.125f; byc *= 0.125f; bzc *= 0.125f;
            const float den = bxc * bxc + byc * byc + bzc * bzc + EPS;
            sd += __fdividef(num * num, den);
        }
    }

    // ---- deterministic block reduction ----
    __shared__ float shb[NT], shp[NT], shd[NT];
    const int tid = threadIdx.x;
    shb[tid] = sb;
    shp[tid] = sp;
    shd[tid] = sd;
    __syncthreads();
    for (int s = NT / 2; s > 0; s >>= 1) {
        if (tid < s) {
            shb[tid] += shb[tid + s];
            shp[tid] += shp[tid + s];
            shd[tid] += shd[tid + s];
        }
        __syncthreads();
    }

    __shared__ bool isLast;
    if (tid == 0) {
        g_pb[blockIdx.x] = shb[0];
        g_pp[blockIdx.x] = shp[0];
        g_pd[blockIdx.x] = shd[0];
        __threadfence();
        isLast = (atomicAdd(&g_cnt, 1u) == NB - 1);
    }
    __syncthreads();

    // ---- last block: final deterministic reduce in double ----
    if (isLast) {
        __threadfence();
        __shared__ double rb[NT], rp[NT], rd[NT];
        double db = 0.0, dp = 0.0, dd = 0.0;
        for (int i = tid; i < NB; i += NT) {
            db += (double)__ldcg(&g_pb[i]);
            dp += (double)__ldcg(&g_pp[i]);
            dd += (double)__ldcg(&g_pd[i]);
        }
        rb[tid] = db; rp[tid] = dp; rd[tid] = dd;
        __syncthreads();
        for (int s = NT / 2; s > 0; s >>= 1) {
            if (tid < s) {
                rb[tid] += rb[tid + s];
                rp[tid] += rp[tid + s];
                rd[tid] += rd[tid + s];
            }
            __syncthreads();
        }
        if (tid == 0) {
            const double N = 8388608.0;            // 2*256*256*64
            const double M = 8193150.0;            // 2*255*255*63
            const double loss_b   = rb[0] / N;
            const double loss_p   = rp[0] / N;
            const double loss_div = rd[0] / M * 1.0e4;   // / DX^2 / DY^2
            out[0] = (float)(1000.0 * loss_b + 1000.0 * loss_p);
            out[1] = (float)(100.0 * loss_div);
            g_cnt = 0;                              // reset for graph replay
        }
    }
}

extern "C" void kernel_launch(void* const* d_in, const int* in_sizes, int n_in,
                              void* d_out, int out_size)
{
    const float* outputs = (const float*)d_in[0];
    const float* targets = (const float*)d_in[1];
    float* out = (float*)d_out;
    loss_kernel<<<NB, NT>>>(outputs, targets, out);
}